// round 1
// baseline (speedup 1.0000x reference)
#include <cuda_runtime.h>
#include <cuda_bf16.h>
#include <cstdint>

// Problem constants
#define Bc   16
#define G    8
#define CPER 32
#define CIN  256
#define Jc   64
#define Hc   56
#define Wc   56

// Tiling
#define TILE_ROWS 8     // output rows per block
#define TILE_J    16    // output channels per block
#define IN_ROWS   (TILE_ROWS + 2)   // 10
#define IN_COLS   (Wc + 2)          // 58
#define NTHREADS  (Wc * 4)          // 224

// smem: input tile [32][10][58] + weights [32*9][16]
#define IN_TILE_ELEMS (CPER * IN_ROWS * IN_COLS)   // 18560
#define W_TILE_ELEMS  (CPER * 9 * TILE_J)          // 4608
#define SMEM_FLOATS   (IN_TILE_ELEMS + W_TILE_ELEMS)
#define SMEM_BYTES    (SMEM_FLOATS * 4)            // 92672

__global__ void __launch_bounds__(NTHREADS, 2)
grouped_conv_kernel(const float* __restrict__ x,
                    const float* __restrict__ wgt,
                    const float* __restrict__ bias,
                    const int*   __restrict__ arr,
                    float*       __restrict__ out)
{
    extern __shared__ float smem[];
    float* in_s = smem;                       // [c][rr][cc]
    float* w_s  = smem + IN_TILE_ELEMS;       // [(c*9+tap)][j_local]
    __shared__ int ch_s[CPER];

    const int tx  = threadIdx.x;              // 0..55 (output col)
    const int ty  = threadIdx.y;              // 0..3
    const int tid = ty * Wc + tx;

    const int bg = blockIdx.z;                // 0..127
    const int b  = bg >> 3;
    const int g  = bg & 7;
    const int r0 = blockIdx.y * TILE_ROWS;    // output row base
    const int jb = blockIdx.x * TILE_J;       // output channel base within group

    if (tid < CPER) ch_s[tid] = arr[g * CPER + tid];
    __syncthreads();

    // ---- Stage gathered input tile: 32 channels x 10 rows x 58 cols (zero-padded halo)
    for (int idx = tid; idx < IN_TILE_ELEMS; idx += NTHREADS) {
        int c   = idx / (IN_ROWS * IN_COLS);
        int rem = idx - c * (IN_ROWS * IN_COLS);
        int rr  = rem / IN_COLS;
        int cc  = rem - rr * IN_COLS;
        int grow = r0 - 1 + rr;
        int gcol = cc - 1;
        float v = 0.0f;
        if ((unsigned)grow < (unsigned)Hc && (unsigned)gcol < (unsigned)Wc) {
            v = x[(((size_t)b * CIN + ch_s[c]) * Hc + grow) * Wc + gcol];
        }
        in_s[idx] = v;
    }

    // ---- Stage weights for this block's 16 output channels: [c*9+tap][j_local]
    for (int i = tid; i < W_TILE_ELEMS; i += NTHREADS) {
        int jl  = i / (CPER * 9);
        int rem = i - jl * (CPER * 9);        // c*9 + tap
        w_s[rem * TILE_J + jl] = wgt[(size_t)(g * Jc + jb + jl) * (CPER * 9) + rem];
    }
    __syncthreads();

    // ---- Compute: 8 rows x 4 j-channels per thread
    float acc[TILE_ROWS][4];
#pragma unroll
    for (int r = 0; r < TILE_ROWS; ++r)
#pragma unroll
        for (int jj = 0; jj < 4; ++jj) acc[r][jj] = 0.0f;

    for (int c = 0; c < CPER; ++c) {
        const float* inc = in_s + c * (IN_ROWS * IN_COLS);
        const float* wc  = w_s + c * 9 * TILE_J + ty * 4;
#pragma unroll
        for (int ky = 0; ky < 3; ++ky) {
#pragma unroll
            for (int kx = 0; kx < 3; ++kx) {
                float xv[TILE_ROWS];
#pragma unroll
                for (int r = 0; r < TILE_ROWS; ++r)
                    xv[r] = inc[(r + ky) * IN_COLS + tx + kx];
                const float* wt = wc + (ky * 3 + kx) * TILE_J;
#pragma unroll
                for (int jj = 0; jj < 4; ++jj) {
                    float wv = wt[jj];
#pragma unroll
                    for (int r = 0; r < TILE_ROWS; ++r)
                        acc[r][jj] = fmaf(xv[r], wv, acc[r][jj]);
                }
            }
        }
    }

    // ---- Bias + store (coalesced along tx)
#pragma unroll
    for (int jj = 0; jj < 4; ++jj) {
        int j  = jb + ty * 4 + jj;
        float bv = bias[g * Jc + j];
        size_t obase = (((size_t)b * (G * Jc) + g * Jc + j) * Hc + r0) * Wc + tx;
#pragma unroll
        for (int r = 0; r < TILE_ROWS; ++r) {
            out[obase + (size_t)r * Wc] = acc[r][jj] + bv;
        }
    }
}

extern "C" void kernel_launch(void* const* d_in, const int* in_sizes, int n_in,
                              void* d_out, int out_size)
{
    const float* x    = (const float*)d_in[0];
    const float* wgt  = (const float*)d_in[1];
    const float* bias = (const float*)d_in[2];
    const int*   arr  = (const int*)d_in[3];
    float* out = (float*)d_out;

    cudaFuncSetAttribute(grouped_conv_kernel,
                         cudaFuncAttributeMaxDynamicSharedMemorySize, SMEM_BYTES);

    dim3 grid(Jc / TILE_J, Hc / TILE_ROWS, Bc * G);   // (4, 7, 128)
    dim3 block(Wc, 4, 1);                              // 224 threads
    grouped_conv_kernel<<<grid, block, SMEM_BYTES>>>(x, wgt, bias, arr, out);
}

// round 3
// speedup vs baseline: 1.0043x; 1.0043x over previous
#include <cuda_runtime.h>
#include <cuda_bf16.h>
#include <cstdint>

typedef unsigned long long ull;

// Problem constants
#define Bc   16
#define G    8
#define CPER 32
#define CIN  256
#define Jc   64
#define Hc   56
#define Wc   56

// Tiling
#define TILE_ROWS 8
#define TILE_J    16
#define IN_ROWS   (TILE_ROWS + 2)   // 10
#define IN_COLS   (Wc + 2)          // 58
#define NTHREADS  (Wc * 4)          // 224

#define IN_TILE_ELEMS (CPER * IN_ROWS * IN_COLS)   // 18560
#define W_TILE_ELEMS  (CPER * 9 * TILE_J)          // 4608
#define SMEM_FLOATS   (IN_TILE_ELEMS + W_TILE_ELEMS)
#define SMEM_BYTES    (SMEM_FLOATS * 4)            // 92672

#define FMA2(d, a, b, c) \
    asm("fma.rn.f32x2 %0, %1, %2, %3;" : "=l"(d) : "l"(a), "l"(b), "l"(c))

#define PACKDUP(out, v) \
    asm("mov.b64 %0, {%1, %1};" : "=l"(out) : "r"(__float_as_uint(v)))

#define PACK2(out, lo, hi) \
    asm("mov.b64 %0, {%1, %2};" : "=l"(out) : "r"(__float_as_uint(lo)), "r"(__float_as_uint(hi)))

#define UNPACK2(lo, hi, in) \
    asm("mov.b64 {%0, %1}, %2;" : "=r"(lo), "=r"(hi) : "l"(in))

__global__ void __launch_bounds__(NTHREADS, 2)
grouped_conv_kernel(const float* __restrict__ x,
                    const float* __restrict__ wgt,
                    const float* __restrict__ bias,
                    const int*   __restrict__ arr,
                    float*       __restrict__ out)
{
    extern __shared__ float smem[];
    float* in_s = smem;                       // [c][rr][cc]
    float* w_s  = smem + IN_TILE_ELEMS;       // [(c*9+tap)][j_local], 8B aligned
    __shared__ int ch_s[CPER];

    const int tx  = threadIdx.x;              // 0..55 (output col)
    const int ty  = threadIdx.y;              // 0..3  (j quad)
    const int tid = ty * Wc + tx;

    const int bg = blockIdx.z;                // 0..127
    const int b  = bg >> 3;
    const int g  = bg & 7;
    const int r0 = blockIdx.y * TILE_ROWS;
    const int jb = blockIdx.x * TILE_J;

    if (tid < CPER) ch_s[tid] = arr[g * CPER + tid];
    __syncthreads();

    // ---- Stage gathered input tile (zero-padded halo)
    for (int idx = tid; idx < IN_TILE_ELEMS; idx += NTHREADS) {
        int c   = idx / (IN_ROWS * IN_COLS);
        int rem = idx - c * (IN_ROWS * IN_COLS);
        int rr  = rem / IN_COLS;
        int cc  = rem - rr * IN_COLS;
        int grow = r0 - 1 + rr;
        int gcol = cc - 1;
        float v = 0.0f;
        if ((unsigned)grow < (unsigned)Hc && (unsigned)gcol < (unsigned)Wc) {
            v = x[(((size_t)b * CIN + ch_s[c]) * Hc + grow) * Wc + gcol];
        }
        in_s[idx] = v;
    }

    // ---- Stage weights: [(c*9+tap)][j_local]
    for (int i = tid; i < W_TILE_ELEMS; i += NTHREADS) {
        int jl  = i / (CPER * 9);
        int rem = i - jl * (CPER * 9);
        w_s[rem * TILE_J + jl] = wgt[(size_t)(g * Jc + jb + jl) * (CPER * 9) + rem];
    }
    __syncthreads();

    // ---- Accumulators: 8 rows x 2 packed j-pairs, initialized with bias
    ull acc0[TILE_ROWS], acc1[TILE_ROWS];
    {
        const float* bp = bias + g * Jc + jb + ty * 4;
        float b0 = bp[0], b1 = bp[1], b2 = bp[2], b3 = bp[3];
        ull bp0, bp1;
        PACK2(bp0, b0, b1);
        PACK2(bp1, b2, b3);
#pragma unroll
        for (int r = 0; r < TILE_ROWS; ++r) { acc0[r] = bp0; acc1[r] = bp1; }
    }

    const float* inc = in_s + tx;
    const float* wcc = w_s + ty * 4;

    for (int c = 0; c < CPER; ++c) {
#pragma unroll
        for (int kx = 0; kx < 3; ++kx) {
            // load 10 input column-values once; reuse across ky
            ull xp[IN_ROWS];
#pragma unroll
            for (int i = 0; i < IN_ROWS; ++i) {
                float v = inc[i * IN_COLS + kx];
                PACKDUP(xp[i], v);
            }
#pragma unroll
            for (int ky = 0; ky < 3; ++ky) {
                const float* wt = wcc + (ky * 3 + kx) * TILE_J;
                ull w0 = *(const ull*)(wt);
                ull w1 = *(const ull*)(wt + 2);
#pragma unroll
                for (int r = 0; r < TILE_ROWS; ++r) {
                    FMA2(acc0[r], xp[r + ky], w0, acc0[r]);
                    FMA2(acc1[r], xp[r + ky], w1, acc1[r]);
                }
            }
        }
        inc += IN_ROWS * IN_COLS;
        wcc += 9 * TILE_J;
    }

    // ---- Store (coalesced along tx); bias already folded in
    {
        const int j = jb + ty * 4;
        size_t obase = (((size_t)b * (G * Jc) + g * Jc + j) * Hc + r0) * Wc + tx;
        const size_t jstride = (size_t)Hc * Wc;
#pragma unroll
        for (int r = 0; r < TILE_ROWS; ++r) {
            unsigned int u0, u1, u2, u3;
            UNPACK2(u0, u1, acc0[r]);
            UNPACK2(u2, u3, acc1[r]);
            size_t o = obase + (size_t)r * Wc;
            out[o]               = __uint_as_float(u0);
            out[o + jstride]     = __uint_as_float(u1);
            out[o + 2 * jstride] = __uint_as_float(u2);
            out[o + 3 * jstride] = __uint_as_float(u3);
        }
    }
}

extern "C" void kernel_launch(void* const* d_in, const int* in_sizes, int n_in,
                              void* d_out, int out_size)
{
    const float* x    = (const float*)d_in[0];
    const float* wgt  = (const float*)d_in[1];
    const float* bias = (const float*)d_in[2];
    const int*   arr  = (const int*)d_in[3];
    float* out = (float*)d_out;

    cudaFuncSetAttribute(grouped_conv_kernel,
                         cudaFuncAttributeMaxDynamicSharedMemorySize, SMEM_BYTES);

    dim3 grid(Jc / TILE_J, Hc / TILE_ROWS, Bc * G);   // (4, 7, 128)
    dim3 block(Wc, 4, 1);                              // 224 threads
    grouped_conv_kernel<<<grid, block, SMEM_BYTES>>>(x, wgt, bias, arr, out);
}

// round 5
// speedup vs baseline: 4.1298x; 4.1119x over previous
#include <cuda_runtime.h>
#include <cuda_fp16.h>
#include <cstdint>

// Problem constants
#define Bc   16
#define G    8
#define CPER 32
#define CIN  256
#define Jc   64
#define Hc   56
#define Wc   56
#define HW   (Hc * Wc)          // 3136

// Tiling
#define TILE_OR 4               // output rows per block
#define IN_RW   (TILE_OR + 2)   // 6 staged input rows
#define NCOLS   58              // padded cols
#define NREAL   (IN_RW * NCOLS) // 348 real staged spatial rows
#define NPADR   384             // A rows allocated (max read 224+31+118=373)
#define NSPAT   (TILE_OR * NCOLS) // 232 output spatial (padded)
#define NTHREADS 256

// smem (dynamic, 1024-aligned): A [384][64B] then B [9][64][64B]
#define SM_A 0
#define SM_B (NPADR * 64)                 // 24576
#define SMEM_USED (SM_B + 9 * Jc * 64)    // 61440
#define SMEM_BYTES (SMEM_USED + 1024)

#define SWZ64(o) ((o) ^ (((o) >> 3) & 0x30))

__device__ __forceinline__ uint32_t smem_u32(const void* p) {
    uint32_t a;
    asm("{ .reg .u64 t; cvta.to.shared.u64 t, %1; cvt.u32.u64 %0, t; }"
        : "=r"(a) : "l"(p));
    return a;
}

#define LDMX4(r0, r1, r2, r3, a) \
    asm volatile("ldmatrix.sync.aligned.m8n8.x4.shared.b16 {%0,%1,%2,%3}, [%4];" \
                 : "=r"(r0), "=r"(r1), "=r"(r2), "=r"(r3) : "r"(a))

#define MMA16816(d, a0, a1, a2, a3, b0, b1) \
    asm volatile("mma.sync.aligned.m16n8k16.row.col.f32.f16.f16.f32 " \
                 "{%0,%1,%2,%3}, {%4,%5,%6,%7}, {%8,%9}, {%0,%1,%2,%3};" \
                 : "+f"((d)[0]), "+f"((d)[1]), "+f"((d)[2]), "+f"((d)[3]) \
                 : "r"(a0), "r"(a1), "r"(a2), "r"(a3), "r"(b0), "r"(b1))

__global__ void __launch_bounds__(NTHREADS, 2)
grouped_conv_hmma_kernel(const float* __restrict__ x,
                         const float* __restrict__ wgt,
                         const float* __restrict__ bias,
                         const int*   __restrict__ arr,
                         float*       __restrict__ out)
{
    extern __shared__ char dsm[];
    __shared__ int   ch_s[CPER];
    __shared__ float bias_s[Jc];

    const int tid  = threadIdx.x;
    const int wid  = tid >> 5;
    const int lane = tid & 31;

    const int g  = blockIdx.x;
    const int r0 = blockIdx.y * TILE_OR;
    const int b  = blockIdx.z;

    // 1024-align the dynamic smem base
    uint32_t raw  = smem_u32(dsm);
    uint32_t base = (raw + 1023u) & ~1023u;
    char* sm = dsm + (base - raw);
    const uint32_t smA = base + SM_A;
    const uint32_t smB = base + SM_B;

    if (tid < CPER) ch_s[tid] = arr[g * CPER + tid];
    if (tid >= 128 && tid < 128 + Jc) bias_s[tid - 128] = bias[g * Jc + tid - 128];
    __syncthreads();

    // ---- Stage A: gathered input, fp16, [n][32ch] 64-B rows, SW64 swizzle
    for (int idx = tid; idx < NPADR * 16; idx += NTHREADS) {
        int cp = idx / NPADR;        // channel pair 0..15
        int n  = idx - cp * NPADR;   // spatial row (consecutive per tid)
        float v0 = 0.0f, v1 = 0.0f;
        if (n < NREAL) {
            int ir = n / NCOLS;
            int ic = n - ir * NCOLS;
            int xr = r0 - 1 + ir;
            int xc = ic - 1;
            if ((unsigned)xr < (unsigned)Hc && (unsigned)xc < (unsigned)Wc) {
                const float* xp = x + (size_t)b * CIN * HW + (size_t)xr * Wc + xc;
                v0 = xp[(size_t)ch_s[2 * cp]     * HW];
                v1 = xp[(size_t)ch_s[2 * cp + 1] * HW];
            }
        }
        __half2 h = __floats2half2_rn(v0, v1);
        *(__half2*)(sm + SM_A + SWZ64((uint32_t)(n * 64 + cp * 4))) = h;
    }

    // ---- Stage B: 9 per-tap weight tiles [j][32c] fp16, 64-B rows, SW64
    for (int idx = tid; idx < 9 * Jc * 16; idx += NTHREADS) {
        int tap = idx >> 10;
        int rem = idx & 1023;
        int j   = rem >> 4;
        int cp  = rem & 15;
        const float* wp = wgt + ((size_t)(g * Jc + j) * CPER) * 9 + tap;
        float v0 = wp[(size_t)(2 * cp) * 9];
        float v1 = wp[(size_t)(2 * cp + 1) * 9];
        __half2 h = __floats2half2_rn(v0, v1);
        *(__half2*)(sm + SM_B + tap * 4096 + SWZ64((uint32_t)(j * 64 + cp * 4))) = h;
    }
    __syncthreads();

    // ---- MMA mainloop: each warp M=32 spatial, N=64 j, K=9 taps x 32 ch
    const int m0 = wid * 32;
    float d[2][8][4];
#pragma unroll
    for (int mt = 0; mt < 2; ++mt)
#pragma unroll
        for (int nt = 0; nt < 8; ++nt)
#pragma unroll
            for (int k = 0; k < 4; ++k) d[mt][nt][k] = 0.0f;

    const int arow  = (lane & 7) + ((lane >> 3) & 1) * 8;
    const int akseg = lane >> 4;
    const int brow  = (lane & 7) + (lane >> 4) * 8;
    const int bkseg = (lane >> 3) & 1;

#pragma unroll
    for (int ky = 0; ky < 3; ++ky) {
#pragma unroll
        for (int kx = 0; kx < 3; ++kx) {
            const int dlt = ky * NCOLS + kx;
            const uint32_t btap = smB + (ky * 3 + kx) * 4096;
#pragma unroll
            for (int ks = 0; ks < 2; ++ks) {
                uint32_t af[2][4];
#pragma unroll
                for (int mt = 0; mt < 2; ++mt) {
                    uint32_t a = smA + SWZ64((uint32_t)((m0 + mt * 16 + arow + dlt) * 64
                                                        + ks * 32 + akseg * 16));
                    LDMX4(af[mt][0], af[mt][1], af[mt][2], af[mt][3], a);
                }
                uint32_t bf[8][2];
#pragma unroll
                for (int nt = 0; nt < 4; ++nt) {
                    uint32_t a = btap + SWZ64((uint32_t)((nt * 16 + brow) * 64
                                                         + ks * 32 + bkseg * 16));
                    LDMX4(bf[2 * nt][0], bf[2 * nt][1], bf[2 * nt + 1][0], bf[2 * nt + 1][1], a);
                }
#pragma unroll
                for (int mt = 0; mt < 2; ++mt)
#pragma unroll
                    for (int nt = 0; nt < 8; ++nt)
                        MMA16816(d[mt][nt], af[mt][0], af[mt][1], af[mt][2], af[mt][3],
                                 bf[nt][0], bf[nt][1]);
            }
        }
    }

    // ---- Epilogue: transpose through smem (reuse A/B region), coalesced stores
    __syncthreads();
    float* smO = (float*)sm;               // [j][233] floats = 59648 B
#pragma unroll
    for (int mt = 0; mt < 2; ++mt) {
        int row = m0 + mt * 16 + (lane >> 2);
#pragma unroll
        for (int nt = 0; nt < 8; ++nt) {
            int j = nt * 8 + (lane & 3) * 2;
            if (row < NSPAT) {
                smO[j * 233 + row]       = d[mt][nt][0];
                smO[(j + 1) * 233 + row] = d[mt][nt][1];
            }
            if (row + 8 < NSPAT) {
                smO[j * 233 + row + 8]       = d[mt][nt][2];
                smO[(j + 1) * 233 + row + 8] = d[mt][nt][3];
            }
        }
    }
    __syncthreads();

    {
        float* obase = out + ((size_t)b * (G * Jc) + g * Jc) * HW + (size_t)r0 * Wc;
        for (int idx = tid; idx < Jc * TILE_OR * Wc; idx += NTHREADS) {
            int j  = idx / (TILE_OR * Wc);
            int r  = idx - j * (TILE_OR * Wc);
            int orow = r / Wc;
            int oc   = r - orow * Wc;
            obase[(size_t)j * HW + orow * Wc + oc] =
                smO[j * 233 + orow * NCOLS + oc] + bias_s[j];
        }
    }
}

extern "C" void kernel_launch(void* const* d_in, const int* in_sizes, int n_in,
                              void* d_out, int out_size)
{
    const float* x    = (const float*)d_in[0];
    const float* wgt  = (const float*)d_in[1];
    const float* bias = (const float*)d_in[2];
    const int*   arr  = (const int*)d_in[3];
    float* out = (float*)d_out;

    cudaFuncSetAttribute(grouped_conv_hmma_kernel,
                         cudaFuncAttributeMaxDynamicSharedMemorySize, SMEM_BYTES);

    dim3 grid(G, Hc / TILE_OR, Bc);   // (8, 14, 16) = 1792 blocks
    grouped_conv_hmma_kernel<<<grid, NTHREADS, SMEM_BYTES>>>(x, wgt, bias, arr, out);
}